// round 1
// baseline (speedup 1.0000x reference)
#include <cuda_runtime.h>
#include <math.h>

#define B_   16
#define H_   512
#define W_   512
#define NPIX (B_ * H_ * W_)
#define BIGF 100000000.0f

// ---------------- scratch (device globals; no allocation) ----------------
__device__ float  g_g[NPIX];          // vertical squared distances g = min(d1^2, BIG)
__device__ float  g_rowsf[B_ * W_];   // f at h==b rows (squared)
__device__ int    g_maxf[B_];         // per-batch max of f (float bits, f>=0)
__device__ double g_acc[4];           // [wmse_sum, sum_p, sum_t, sum_pt]

// ---------------- K0: zero accumulators ----------------
__global__ void k_zero() {
    int i = threadIdx.x;
    if (i < B_) g_maxf[i] = 0;        // bits of +0.0f
    if (i < 4)  g_acc[i]  = 0.0;
}

// ---------------- K1: vertical pass (thread per column) ----------------
__global__ void k_vert(const float* __restrict__ t) {
    int tid = blockIdx.x * blockDim.x + threadIdx.x;
    if (tid >= B_ * W_) return;
    int b = tid / W_;
    int w = tid % W_;
    const float* tb = t + (size_t)b * H_ * W_ + w;
    float* gb = g_g + (size_t)b * H_ * W_ + w;

    // downward scan: d = (t==0) ? 0 : d+1, init BIG (fp32, matches reference)
    float d = BIGF;
    #pragma unroll 4
    for (int h = 0; h < H_; ++h) {
        float z = tb[(size_t)h * W_];
        d = (z == 0.0f) ? 0.0f : (d + 1.0f);
        gb[(size_t)h * W_] = d;
    }
    // upward scan + combine; note stored d==0 <=> t==0
    float d2 = BIGF;
    #pragma unroll 4
    for (int h = H_ - 1; h >= 0; --h) {
        float dn = gb[(size_t)h * W_];
        d2 = (dn == 0.0f) ? 0.0f : (d2 + 1.0f);
        float dm = fminf(dn, d2);
        gb[(size_t)h * W_] = fminf(dm * dm, BIGF);
    }
}

// ---------------- K2: row transform (block per row, early-break window) ----------------
__global__ void k_row() {
    __shared__ float srow[W_];
    __shared__ float smax[16];
    int bh = blockIdx.x;               // 0 .. B_*H_-1
    int b  = bh / H_;
    int h  = bh % H_;
    int y  = threadIdx.x;              // 0..511

    const float* grow = g_g + (size_t)bh * W_;
    srow[y] = grow[y];
    __syncthreads();

    float best = srow[y];
    for (int r = 1; r < W_; ++r) {
        float r2 = (float)(r * r);
        if (r2 >= best) break;         // exact: candidates >= r2 can't improve
        int jl = y - r, jr = y + r;
        if (jl >= 0)  best = fminf(best, srow[jl] + r2);
        if (jr < W_)  best = fminf(best, srow[jr] + r2);
    }

    if (h == b) g_rowsf[b * W_ + y] = best;   // row used for 'rows'

    // block max reduce -> per-batch atomicMax (float-as-int, nonnegative)
    float m = best;
    #pragma unroll
    for (int o = 16; o > 0; o >>= 1)
        m = fmaxf(m, __shfl_down_sync(0xffffffffu, m, o));
    if ((threadIdx.x & 31) == 0) smax[threadIdx.x >> 5] = m;
    __syncthreads();
    if (threadIdx.x < 16) {
        m = smax[threadIdx.x];
        #pragma unroll
        for (int o = 8; o > 0; o >>= 1)
            m = fmaxf(m, __shfl_down_sync(0xffffu, m, o));
        if (threadIdx.x == 0)
            atomicMax(&g_maxf[b], __float_as_int(m));
    }
}

// ---------------- K3: fused weighted MSE + dice partial sums ----------------
// grid: (128, 16), block 256, 8 pixels/thread (stride 256)
__global__ void k_main(const float* __restrict__ in, const float* __restrict__ tg) {
    int b = blockIdx.y;
    float v = sqrtf(__int_as_float(g_maxf[b]));
    int pix0 = blockIdx.x * 2048 + threadIdx.x;
    size_t base = (size_t)b * H_ * W_;

    float sw = 0.f, sp = 0.f, st = 0.f, spt = 0.f;
    #pragma unroll
    for (int k = 0; k < 8; ++k) {
        int pix = pix0 + k * 256;
        size_t i = base + pix;
        float x = in[i];
        float t = tg[i];
        int   y = pix & (W_ - 1);
        float rowv = sqrtf(g_rowsf[b * W_ + y]);
        float weight = ((t != 0.0f) ? (v - rowv) : 0.0f) + 0.001f;
        float diff = x - t;
        sw  += weight * diff * diff;
        float p = 1.0f / (1.0f + expf(-x));
        sp  += p;
        st  += t;
        spt += p * t;
    }

    // block reduce 4 sums
    __shared__ float red[4][8];
    float vals[4] = {sw, sp, st, spt};
    #pragma unroll
    for (int q = 0; q < 4; ++q) {
        float s = vals[q];
        #pragma unroll
        for (int o = 16; o > 0; o >>= 1)
            s += __shfl_down_sync(0xffffffffu, s, o);
        if ((threadIdx.x & 31) == 0) red[q][threadIdx.x >> 5] = s;
    }
    __syncthreads();
    if (threadIdx.x < 8) {
        // 8 warps per block
        #pragma unroll
        for (int q = 0; q < 4; ++q) {
            float s = red[q][threadIdx.x];
            #pragma unroll
            for (int o = 4; o > 0; o >>= 1)
                s += __shfl_down_sync(0xffu, s, o);
            if (threadIdx.x == 0)
                atomicAdd(&g_acc[q], (double)s);
        }
    }
}

// ---------------- K4: finalize ----------------
__global__ void k_final(float* __restrict__ out, int out_size) {
    if (threadIdx.x != 0 || blockIdx.x != 0) return;
    double wmse = g_acc[0] / (double)NPIX;
    double P = g_acc[1], T = g_acc[2], I = g_acc[3];
    double dice = 1.0 - (2.0 * I + 1e-6) / (P + T + 1e-6);
    if (out_size >= 1) out[0] = (float)(0.6 * wmse);
    if (out_size >= 2) out[1] = (float)(1.0 * dice);
}

// ---------------- launch ----------------
extern "C" void kernel_launch(void* const* d_in, const int* in_sizes, int n_in,
                              void* d_out, int out_size) {
    const float* inputs  = (const float*)d_in[0];
    const float* targets = (const float*)d_in[1];
    float* out = (float*)d_out;

    k_zero<<<1, 32>>>();
    k_vert<<<(B_ * W_ + 255) / 256, 256>>>(targets);
    k_row<<<B_ * H_, W_>>>();
    dim3 g3(128, B_);
    k_main<<<g3, 256>>>(inputs, targets);
    k_final<<<1, 32>>>(out, out_size);
}

// round 2
// speedup vs baseline: 2.0307x; 2.0307x over previous
#include <cuda_runtime.h>
#include <math.h>

#define B_    16
#define H_    512
#define W_    512
#define NPIX  (B_ * H_ * W_)
#define BIGF  100000000.0f

// ---------------- scratch (device globals; no allocation) ----------------
__device__ float  g_g[NPIX];          // vertical squared distances g = min(d1^2, BIG)
__device__ float  g_rowsf[B_ * W_];   // f at h==b rows (squared)
__device__ int    g_maxf[B_];         // per-batch max of f (float bits, f>=0)
__device__ double g_acc[4];           // [wmse_sum, sum_p, sum_t, sum_pt]

// ================= K1: vertical distance via bitmask chunks =================
// Block: 512 threads = 64 columns x 8 chunks of 64 rows. Grid: (W/64, B) = (8,16).
__global__ void k_vert(const float* __restrict__ t) {
    __shared__ int s_last[8][64];   // last zero index in chunk (global row), or -BIG
    __shared__ int s_first[8][64];  // first zero index in chunk, or +BIG

    const int c_tile = blockIdx.x;          // 0..7
    const int b      = blockIdx.y;          // 0..15
    const int c      = threadIdx.x & 63;    // column within tile
    const int k      = threadIdx.x >> 6;    // chunk 0..7
    const int col    = c_tile * 64 + c;
    const int r0     = k * 64;

    // zero accumulators once (safe: consumed only by later kernels)
    if (blockIdx.x == 0 && blockIdx.y == 0) {
        if (threadIdx.x < B_) g_maxf[threadIdx.x] = 0;
        if (threadIdx.x < 4)  g_acc[threadIdx.x]  = 0.0;
    }

    const float* tb = t + (size_t)b * H_ * W_ + col;
    float* gb = g_g + (size_t)b * H_ * W_ + col;

    // build 64-row zero bitmask (loads coalesced across warp lanes)
    unsigned long long zbits = 0ull;
    #pragma unroll
    for (int i = 0; i < 64; ++i) {
        float z = tb[(size_t)(r0 + i) * W_];
        if (z == 0.0f) zbits |= (1ull << i);
    }

    const int SENT = 1 << 28;
    int lastz  = zbits ? (r0 + 63 - __clzll(zbits)) : -SENT;
    int firstz = zbits ? (r0 + __ffsll(zbits) - 1)  :  SENT;
    s_last[k][c]  = lastz;
    s_first[k][c] = firstz;
    __syncthreads();

    int lastAbove = -SENT;          // last zero strictly above this chunk
    #pragma unroll
    for (int kk = 0; kk < 8; ++kk)
        if (kk < k) lastAbove = max(lastAbove, s_last[kk][c]);
    int nextBelow = SENT;           // first zero strictly below this chunk
    #pragma unroll
    for (int kk = 0; kk < 8; ++kk)
        if (kk > k) nextBelow = min(nextBelow, s_first[kk][c]);

    // emit g = min(dist^2, BIG)
    #pragma unroll
    for (int i = 0; i < 64; ++i) {
        int r = r0 + i;
        unsigned long long below = zbits & ((i == 63) ? ~0ull : ((2ull << i) - 1ull));
        int lz = below ? (r0 + 63 - __clzll(below)) : lastAbove;
        unsigned long long above = zbits >> i;
        int nz = above ? (r + __ffsll(above) - 1) : nextBelow;
        int dmin = min(r - lz, nz - r);
        float g = (dmin > 511) ? BIGF : (float)(dmin * dmin);
        gb[(size_t)r * W_] = g;
    }
}

// ================= K2: row transform (block per row, early-break) =================
__global__ void k_row() {
    __shared__ float srow[W_];
    __shared__ float smax[16];
    int bh = blockIdx.x;               // 0 .. B_*H_-1
    int b  = bh / H_;
    int h  = bh % H_;
    int y  = threadIdx.x;

    const float* grow = g_g + (size_t)bh * W_;
    srow[y] = grow[y];
    __syncthreads();

    float best = srow[y];
    for (int r = 1; r < W_; ++r) {
        float r2 = (float)(r * r);
        if (r2 >= best) break;         // exact: all further candidates >= best
        int jl = y - r, jr = y + r;
        if (jl >= 0)  best = fminf(best, srow[jl] + r2);
        if (jr < W_)  best = fminf(best, srow[jr] + r2);
    }

    if (h == b) g_rowsf[b * W_ + y] = best;

    float m = best;
    #pragma unroll
    for (int o = 16; o > 0; o >>= 1)
        m = fmaxf(m, __shfl_down_sync(0xffffffffu, m, o));
    if ((threadIdx.x & 31) == 0) smax[threadIdx.x >> 5] = m;
    __syncthreads();
    if (threadIdx.x < 16) {
        m = smax[threadIdx.x];
        #pragma unroll
        for (int o = 8; o > 0; o >>= 1)
            m = fmaxf(m, __shfl_down_sync(0xffffu, m, o));
        if (threadIdx.x == 0)
            atomicMax(&g_maxf[b], __float_as_int(m));
    }
}

// ================= K3: fused weighted MSE + dice (float4) =================
// grid (64, B), block 256; 4 float4 per thread, grid-stride over 65536 float4s.
__global__ void k_main(const float4* __restrict__ in4, const float4* __restrict__ tg4) {
    __shared__ float s_wb[W_];          // v - sqrt(rowsf[y])
    __shared__ float red[4][8];

    const int b = blockIdx.y;
    const float v = sqrtf(__int_as_float(g_maxf[b]));
    // fill weight-base table
    {
        int t0 = threadIdx.x;
        s_wb[t0]       = v - sqrtf(g_rowsf[b * W_ + t0]);
        s_wb[t0 + 256] = v - sqrtf(g_rowsf[b * W_ + t0 + 256]);
    }
    __syncthreads();

    const size_t base4 = (size_t)b * (H_ * W_ / 4);
    const int q0 = blockIdx.x * 256 + threadIdx.x;   // float4 lane position
    const float4* wb4 = (const float4*)s_wb;

    float sw = 0.f, sp = 0.f, st = 0.f, spt = 0.f;
    #pragma unroll
    for (int k = 0; k < 4; ++k) {
        int fi = q0 + k * 16384;                     // float4 index within image
        float4 x = in4[base4 + fi];
        float4 t = tg4[base4 + fi];
        float4 wb = wb4[fi & 127];                   // y0 = (fi*4)&511 -> float4 idx fi&127

        float px, wgt, d;
        d = x.x - t.x; wgt = ((t.x != 0.f) ? wb.x : 0.f) + 0.001f; sw += wgt * d * d;
        px = 1.f / (1.f + __expf(-x.x)); sp += px; st += t.x; spt += px * t.x;
        d = x.y - t.y; wgt = ((t.y != 0.f) ? wb.y : 0.f) + 0.001f; sw += wgt * d * d;
        px = 1.f / (1.f + __expf(-x.y)); sp += px; st += t.y; spt += px * t.y;
        d = x.z - t.z; wgt = ((t.z != 0.f) ? wb.z : 0.f) + 0.001f; sw += wgt * d * d;
        px = 1.f / (1.f + __expf(-x.z)); sp += px; st += t.z; spt += px * t.z;
        d = x.w - t.w; wgt = ((t.w != 0.f) ? wb.w : 0.f) + 0.001f; sw += wgt * d * d;
        px = 1.f / (1.f + __expf(-x.w)); sp += px; st += t.w; spt += px * t.w;
    }

    float vals[4] = {sw, sp, st, spt};
    #pragma unroll
    for (int q = 0; q < 4; ++q) {
        float s = vals[q];
        #pragma unroll
        for (int o = 16; o > 0; o >>= 1)
            s += __shfl_down_sync(0xffffffffu, s, o);
        if ((threadIdx.x & 31) == 0) red[q][threadIdx.x >> 5] = s;
    }
    __syncthreads();
    if (threadIdx.x < 8) {
        #pragma unroll
        for (int q = 0; q < 4; ++q) {
            float s = red[q][threadIdx.x];
            #pragma unroll
            for (int o = 4; o > 0; o >>= 1)
                s += __shfl_down_sync(0xffu, s, o);
            if (threadIdx.x == 0)
                atomicAdd(&g_acc[q], (double)s);
        }
    }
}

// ================= K4: finalize =================
__global__ void k_final(float* __restrict__ out, int out_size) {
    if (threadIdx.x != 0 || blockIdx.x != 0) return;
    double wmse = g_acc[0] / (double)NPIX;
    double P = g_acc[1], T = g_acc[2], I = g_acc[3];
    double dice = 1.0 - (2.0 * I + 1e-6) / (P + T + 1e-6);
    if (out_size >= 1) out[0] = (float)(0.6 * wmse);
    if (out_size >= 2) out[1] = (float)(1.0 * dice);
}

// ---------------- launch ----------------
extern "C" void kernel_launch(void* const* d_in, const int* in_sizes, int n_in,
                              void* d_out, int out_size) {
    const float* inputs  = (const float*)d_in[0];
    const float* targets = (const float*)d_in[1];
    float* out = (float*)d_out;

    dim3 gv(W_ / 64, B_);
    k_vert<<<gv, 512>>>(targets);
    k_row<<<B_ * H_, W_>>>();
    dim3 g3(64, B_);
    k_main<<<g3, 256>>>((const float4*)inputs, (const float4*)targets);
    k_final<<<1, 32>>>(out, out_size);
}